// round 1
// baseline (speedup 1.0000x reference)
#include <cuda_runtime.h>

#define NC 16       // codebooks
#define NK 16       // prototypes per codebook
#define NM 16       // output rows (M)
#define ND 64       // feature dim
#define NSPL 4      // tree depth
#define LSTRIDE 17  // padded LUT row stride (conflict-free: 17*enc mod 32 distinct for enc 0..15)
#define TB 128      // rows (=threads) per block

// LUT produced by lut_kernel, consumed by main kernel (same stream -> ordered)
__device__ float g_lut[NC * NK * NM];

// ---------------------------------------------------------------------------
// Kernel 1: lut[c,k,m] = sum_d B[m,d] * prototypes[c,k,d]
// One block per codebook c, 256 threads = (k,m) pairs.
// ---------------------------------------------------------------------------
__global__ void lut_kernel(const float* __restrict__ B, const float* __restrict__ P) {
    __shared__ float Bs[NM][ND + 1];
    __shared__ float Ps[NK][ND + 1];
    int c = blockIdx.x, tid = threadIdx.x;
    for (int i = tid; i < NM * ND; i += 256) Bs[i >> 6][i & 63] = B[i];
    for (int i = tid; i < NK * ND; i += 256) Ps[i >> 6][i & 63] = P[c * NK * ND + i];
    __syncthreads();
    int k = tid >> 4, m = tid & 15;
    float acc = 0.f;
#pragma unroll
    for (int d = 0; d < ND; d++) acc = fmaf(Bs[m][d], Ps[k][d], acc);
    g_lut[(c * NK + k) * NM + m] = acc;
}

// ---------------------------------------------------------------------------
// Kernel 2: encode + LUT gather-sum.
// Each thread owns one row n: walks the 4-level tree for each of 16 codebooks
// (exact fp32 compares, identical to reference), accumulates 16 LUT rows into
// registers, writes out[m*N + n] (coalesced per m).
// ---------------------------------------------------------------------------
__global__ void __launch_bounds__(TB) maddness_kernel(
    const float* __restrict__ A,
    const int*   __restrict__ sdim_g,   // [C,NSPL]
    const float* __restrict__ sval_g,   // [C,NSPL,8]
    float*       __restrict__ out,      // [M,N]
    int N)
{
    extern __shared__ float smem[];
    float* lut_s = smem;                               // NC*NK*LSTRIDE floats (4352)
    float* sval  = lut_s + NC * NK * LSTRIDE;          // 512 floats
    int*   sdim  = (int*)(sval + NC * NSPL * 8);       // 64 ints
    float* As    = (float*)(sdim + NC * NSPL);         // TB * (ND+1) floats

    int tid = threadIdx.x;

    // Stage LUT with stride-17 remap (conflict-free lookups later)
    for (int i = tid; i < NC * NK * NM; i += TB) {
        int ck = i >> 4, m = i & 15;
        lut_s[ck * LSTRIDE + m] = g_lut[i];
    }
    for (int i = tid; i < NC * NSPL * 8; i += TB) sval[i] = sval_g[i];
    if (tid < NC * NSPL) sdim[tid] = sdim_g[tid];

    long long base = (long long)blockIdx.x * TB;
    int rows = (N - base < TB) ? (int)(N - base) : TB;

    // Stage A tile: coalesced float4 global reads, padded scalar SMEM stores
    const float4* A4 = (const float4*)(A + base * ND);
    int n4 = rows * (ND / 4);
#pragma unroll
    for (int j = 0; j < ND / 4; j++) {   // TB*ND/4 / TB = 16 iterations
        int idx4 = j * TB + tid;
        if (idx4 < n4) {
            float4 v = A4[idx4];
            int row = idx4 >> 4;
            int d0  = (idx4 & 15) << 2;
            float* p = As + row * (ND + 1) + d0;
            p[0] = v.x; p[1] = v.y; p[2] = v.z; p[3] = v.w;
        }
    }
    __syncthreads();

    if (tid >= rows) return;

    const float* arow = As + tid * (ND + 1);
    float acc[NM];
#pragma unroll
    for (int m = 0; m < NM; m++) acc[m] = 0.f;

#pragma unroll
    for (int c = 0; c < NC; c++) {
        int gid = 0;
#pragma unroll
        for (int i = 0; i < NSPL; i++) {
            int   d = sdim[c * NSPL + i];                  // uniform -> broadcast
            float x = arow[d];                             // bank (tid+d)%32: conflict-free
            float v = sval[(c * NSPL + i) * 8 + gid];      // distinct gid -> distinct banks
            gid = (gid << 1) + (x > v ? 1 : 0);
        }
        const float* lr = lut_s + (c * NK + gid) * LSTRIDE; // stride-17: conflict-free
#pragma unroll
        for (int m = 0; m < NM; m++) acc[m] += lr[m];
    }

    long long n = base + tid;
#pragma unroll
    for (int m = 0; m < NM; m++) out[(long long)m * N + n] = acc[m];
}

// ---------------------------------------------------------------------------
extern "C" void kernel_launch(void* const* d_in, const int* in_sizes, int n_in,
                              void* d_out, int out_size) {
    const float* A     = (const float*)d_in[0];
    const float* B     = (const float*)d_in[1];
    const float* P     = (const float*)d_in[2];
    const int*   sdims = (const int*)d_in[3];
    const float* svals = (const float*)d_in[4];
    float* out = (float*)d_out;
    int N = in_sizes[0] / ND;

    lut_kernel<<<NC, 256>>>(B, P);

    size_t smem_bytes = (size_t)(NC * NK * LSTRIDE + NC * NSPL * 8) * 4
                      + (size_t)(NC * NSPL) * 4
                      + (size_t)TB * (ND + 1) * 4;   // = 52,992 B
    cudaFuncSetAttribute(maddness_kernel,
                         cudaFuncAttributeMaxDynamicSharedMemorySize,
                         (int)smem_bytes);

    int blocks = (N + TB - 1) / TB;
    maddness_kernel<<<blocks, TB, smem_bytes>>>(A, sdims, svals, out, N);
}

// round 2
// speedup vs baseline: 1.1231x; 1.1231x over previous
#include <cuda_runtime.h>

#define NC 16       // codebooks
#define NK 16       // prototypes per codebook
#define NM 16       // output rows (M)
#define ND 64       // feature dim
#define NSPL 4      // tree depth
#define LSTR 18     // LUT row stride (even for float2 loads; (9*gid+j) mod 16 bijective -> conflict-free LDS.64)
#define TB 256      // threads = rows per tile

__device__ float g_lut[NC * NK * NM];

// ---------------------------------------------------------------------------
// Kernel 1: lut[c,k,m] = sum_d B[m,d] * prototypes[c,k,d]
// ---------------------------------------------------------------------------
__global__ void lut_kernel(const float* __restrict__ B, const float* __restrict__ P) {
    __shared__ float Bs[NM][ND + 1];
    __shared__ float Ps[NK][ND + 1];
    int c = blockIdx.x, tid = threadIdx.x;
    for (int i = tid; i < NM * ND; i += 256) Bs[i >> 6][i & 63] = B[i];
    for (int i = tid; i < NK * ND; i += 256) Ps[i >> 6][i & 63] = P[c * NK * ND + i];
    __syncthreads();
    int k = tid >> 4, m = tid & 15;
    float acc = 0.f;
#pragma unroll
    for (int d = 0; d < ND; d++) acc = fmaf(Bs[m][d], Ps[k][d], acc);
    g_lut[(c * NK + k) * NM + m] = acc;
}

// ---------------------------------------------------------------------------
// cp.async helpers
// ---------------------------------------------------------------------------
__device__ __forceinline__ unsigned smem_u32(const void* p) {
    unsigned a;
    asm("{ .reg .u64 t; cvta.to.shared.u64 t, %1; cvt.u32.u64 %0, t; }" : "=r"(a) : "l"(p));
    return a;
}
__device__ __forceinline__ void cpa8(unsigned dst, const void* src) {
    asm volatile("cp.async.ca.shared.global [%0], [%1], 8;\n" :: "r"(dst), "l"(src));
}
__device__ __forceinline__ void cpa_commit() { asm volatile("cp.async.commit_group;\n"); }
__device__ __forceinline__ void cpa_wait1() { asm volatile("cp.async.wait_group 1;\n"); }

// ---------------------------------------------------------------------------
// Kernel 2: persistent encode + LUT gather-sum, double-buffered A tiles.
// A tile layout: 8B chunk ch of row r stored at slot (ch ^ (r&31)) within the
// row's 64-float span -> uniform-d reads hit 16 distinct banks (2-way max).
// ---------------------------------------------------------------------------
__global__ void __launch_bounds__(TB, 1) maddness_kernel(
    const float* __restrict__ A,
    const int*   __restrict__ sdim_g,   // [C,NSPL]
    const float* __restrict__ sval_g,   // [C,NSPL,8]
    float*       __restrict__ out,      // [M,N]
    int N, int ntiles)
{
    extern __shared__ float smem[];
    float* lut_s = smem;                              // 16*16*18 = 4608 floats
    float* sval  = lut_s + NC * NK * LSTR;            // 512 floats
    int*   sdim  = (int*)(sval + NC * NSPL * 8);      // 64 ints
    float* Ab    = (float*)(sdim + 64);               // 2 * 256 * 64 floats (8B-aligned)

    const int tid = threadIdx.x;
    const long long Nll = N;

    // One-time staging per CTA
    for (int i = tid; i < NC * NK * NM; i += TB)
        lut_s[(i >> 4) * LSTR + (i & 15)] = g_lut[i];
    for (int i = tid; i < NC * NSPL * 8; i += TB) sval[i] = sval_g[i];
    if (tid < NC * NSPL) sdim[tid] = sdim_g[tid];

    const unsigned Ab_u = smem_u32(Ab);
    const int stride = gridDim.x;

    // --- tile copy: 32 x 8B chunks per thread, coalesced 256B per warp ---
    auto copy_tile = [&](int buf, int t) {
        long long base = (long long)t * TB;
        unsigned sb = Ab_u + (unsigned)buf * (TB * ND * 4);
        const float* gb = A + base * ND;
#pragma unroll
        for (int j = 0; j < 32; j++) {
            int idx = j * TB + tid;          // chunk index within tile
            int r   = idx >> 5;              // row 0..255
            int ch  = idx & 31;              // 8B chunk 0..31
            if (base + r < N)
                cpa8(sb + (unsigned)(r * ND + ((ch ^ (r & 31)) << 1)) * 4,
                     gb + (long long)r * ND + ch * 2);
        }
    };

    int t0 = blockIdx.x;
    if (t0 < ntiles) copy_tile(0, t0);
    cpa_commit();

    int buf = 0;
    for (int t = t0; t < ntiles; t += stride, buf ^= 1) {
        int tn = t + stride;
        if (tn < ntiles) copy_tile(buf ^ 1, tn);
        cpa_commit();
        cpa_wait1();            // tile t's group complete
        __syncthreads();        // also orders LUT/sval staging on first iter

        long long base = (long long)t * TB;
        int r = tid;
        if (base + r < N) {
            const float* arow = Ab + buf * (TB * ND) + r * ND;
            const int rx = r & 31;
            float2 acc[8];
#pragma unroll
            for (int j = 0; j < 8; j++) { acc[j].x = 0.f; acc[j].y = 0.f; }

#pragma unroll
            for (int c = 0; c < NC; c++) {
                int g = 0;
#pragma unroll
                for (int i = 0; i < NSPL; i++) {
                    int   d = sdim[c * NSPL + i];                       // uniform
                    float x = arow[(((d >> 1) ^ rx) << 1) | (d & 1)];   // swizzled, <=2-way
                    float v = sval[(c * NSPL + i) * 8 + g];             // conflict-free
                    g = (g << 1) + (x > v ? 1 : 0);
                }
                const float2* lr = (const float2*)(lut_s + (c * NK + g) * LSTR);
#pragma unroll
                for (int j = 0; j < 8; j++) {                           // LDS.64, conflict-free
                    float2 v2 = lr[j];
                    acc[j].x += v2.x; acc[j].y += v2.y;
                }
            }

            long long n = base + r;
#pragma unroll
            for (int j = 0; j < 8; j++) {
                out[(long long)(2 * j)     * Nll + n] = acc[j].x;
                out[(long long)(2 * j + 1) * Nll + n] = acc[j].y;
            }
        }
        __syncthreads();        // protect buf from next prefetch overwrite
    }
}

// ---------------------------------------------------------------------------
extern "C" void kernel_launch(void* const* d_in, const int* in_sizes, int n_in,
                              void* d_out, int out_size) {
    const float* A     = (const float*)d_in[0];
    const float* B     = (const float*)d_in[1];
    const float* P     = (const float*)d_in[2];
    const int*   sdims = (const int*)d_in[3];
    const float* svals = (const float*)d_in[4];
    float* out = (float*)d_out;
    int N = in_sizes[0] / ND;
    int ntiles = (N + TB - 1) / TB;

    lut_kernel<<<NC, 256>>>(B, P);

    size_t smem_bytes = (size_t)(NC * NK * LSTR + NC * NSPL * 8) * 4
                      + (size_t)(NC * NSPL) * 4
                      + (size_t)2 * TB * ND * 4;     // 151,808 B
    cudaFuncSetAttribute(maddness_kernel,
                         cudaFuncAttributeMaxDynamicSharedMemorySize,
                         (int)smem_bytes);

    int nsm = 148;
    cudaDeviceGetAttribute(&nsm, cudaDevAttrMultiProcessorCount, 0);
    int grid = nsm < ntiles ? nsm : ntiles;

    maddness_kernel<<<grid, TB, smem_bytes>>>(A, sdims, svals, out, N, ntiles);
}